// round 15
// baseline (speedup 1.0000x reference)
#include <cuda_runtime.h>
#include <cstdint>

// ExpandHarmonics: N=2e6 rows, MAX_MULT=5 harmonics per row.
// Output layout (concatenated flattened tuple, float32):
//   [0,15N) hkl_all | [15N,20N) wavelength_all | [20N,25N) d_all | [25N,30N) refl_id

#define HMAX_C 60
#define G_C    121
#define MAX_MULT_C 5
#define BLOCK 128

#define INV_WMIN (1.0f / 0.95f)
#define INV_WMAX 0.8f            // 1/1.25

// gcd table for a,b in [0,12]
__device__ const unsigned char GTAB[169] = {
    0,1,2,3,4,5,6,7,8,9,10,11,12,
    1,1,1,1,1,1,1,1,1,1,1,1,1,
    2,1,2,1,2,1,2,1,2,1,2,1,2,
    3,1,1,3,1,1,3,1,1,3,1,1,3,
    4,1,2,1,4,1,2,1,4,1,2,1,4,
    5,1,1,1,1,5,1,1,1,1,5,1,1,
    6,1,2,3,2,1,6,1,2,3,2,1,6,
    7,1,1,1,1,1,1,7,1,1,1,1,1,
    8,1,2,1,4,1,2,1,8,1,2,1,4,
    9,1,1,3,1,1,3,1,1,9,1,1,3,
    10,1,2,1,2,5,2,1,2,1,10,1,2,
    11,1,1,1,1,1,1,1,1,1,1,11,1,
    12,1,2,3,4,1,6,1,4,3,2,1,12
};

__device__ __forceinline__ int ldg_policy(const int* p, uint64_t policy) {
    int v;
    asm volatile("ld.global.nc.L2::cache_hint.b32 %0, [%1], %2;"
                 : "=r"(v) : "l"(p), "l"(policy));
    return v;
}

__device__ __forceinline__ void bulk_store_s2g_ef(void* gdst, const void* ssrc, int bytes,
                                                  uint64_t policy) {
    uint32_t s = (uint32_t)__cvta_generic_to_shared(ssrc);
    asm volatile("cp.async.bulk.global.shared::cta.bulk_group.L2::cache_hint"
                 " [%0], [%1], %2, %3;"
                 :: "l"(gdst), "r"(s), "r"(bytes), "l"(policy) : "memory");
}

__device__ __forceinline__ void bulk_load_g2s(void* sdst, const void* gsrc, int bytes,
                                              uint32_t mbar) {
    uint32_t s = (uint32_t)__cvta_generic_to_shared(sdst);
    asm volatile("cp.async.bulk.shared::cta.global.mbarrier::complete_tx::bytes"
                 " [%0], [%1], %2, [%3];"
                 :: "r"(s), "l"(gsrc), "r"(bytes), "r"(mbar) : "memory");
}

__global__ __launch_bounds__(BLOCK, 8)
void expand_harmonics_kernel(const int*   __restrict__ asu_id,
                             const int*   __restrict__ hkl,
                             const float* __restrict__ wl,
                             const float* __restrict__ dmin,
                             const float* __restrict__ Bmat,
                             const int*   __restrict__ refl,
                             float*       __restrict__ out,
                             int N)
{
    __shared__ float sB[36];
    __shared__ float srdmin[4];
    __shared__ float srcp[32];
    __shared__ unsigned char sg[169];
    __shared__ __align__(8) uint64_t s_mbar;
    __shared__ __align__(16) int   s_in_asu[BLOCK];       // 512 B
    __shared__ __align__(16) int   s_in_hkl[BLOCK * 3];   // 1536 B
    __shared__ __align__(16) float s_in_wl [BLOCK];       // 512 B
    __shared__ __align__(16) float s_hkl[BLOCK * 15];
    __shared__ __align__(16) float s_wl [BLOCK * 5];
    __shared__ __align__(16) float s_d  [BLOCK * 5];
    __shared__ __align__(16) float s_id [BLOCK * 5];

    const int t = threadIdx.x;
    const uint32_t mbar = (uint32_t)__cvta_generic_to_shared(&s_mbar);

    const int r0 = blockIdx.x * BLOCK;
    const int nv = min(BLOCK, N - r0);
    const bool full = (nv == BLOCK);

    if (t == 0) {
        asm volatile("mbarrier.init.shared.b64 [%0], 1;" :: "r"(mbar));
    }
    if (t < 36)  sB[t] = Bmat[t];
    if (t < 4)   srdmin[t] = 1.0f / dmin[t];
    if (t < 32)  srcp[t] = 1.0f / (float)max(t, 1);
    {
        if (t < 128)       sg[t]       = GTAB[t];
        if (t < 169 - 128) sg[t + 128] = GTAB[t + 128];
    }
    __syncthreads();   // mbarrier init + tables visible

    // ---- Bulk-prefetch this tile's inputs (one TMA op set, no LSU wavefronts) ----
    if (full && t == 0) {
        const int tx = BLOCK * 4 + BLOCK * 12 + BLOCK * 4;   // 2560 B
        asm volatile("mbarrier.arrive.expect_tx.shared.b64 _, [%0], %1;"
                     :: "r"(mbar), "r"(tx));
        bulk_load_g2s(s_in_asu, asu_id + r0,          BLOCK * 4,  mbar);
        bulk_load_g2s(s_in_hkl, hkl + (size_t)r0 * 3, BLOCK * 12, mbar);
        bulk_load_g2s(s_in_wl,  wl + r0,              BLOCK * 4,  mbar);
    }

    uint64_t pol_keep;
    asm volatile("createpolicy.fractional.L2::evict_last.b64 %0, 1.0;" : "=l"(pol_keep));

    if (full) {
        // wait for bulk inputs (acquire orders subsequent LDS)
        uint32_t done;
        asm volatile(
            "{\n\t.reg .pred p;\n\t"
            "mbarrier.try_wait.parity.acquire.cta.shared::cta.b64 p, [%1], 0;\n\t"
            "selp.b32 %0, 1, 0, p;\n\t}"
            : "=r"(done) : "r"(mbar) : "memory");
        if (!done) {
            asm volatile(
                "{\n\t.reg .pred P1;\n\t"
                "WAIT_LOOP_%=:\n\t"
                "mbarrier.try_wait.parity.acquire.cta.shared::cta.b64 P1, [%0], 0, 0x989680;\n\t"
                "@P1 bra.uni WAIT_DONE_%=;\n\t"
                "bra.uni WAIT_LOOP_%=;\n\t"
                "WAIT_DONE_%=:\n\t}"
                :: "r"(mbar) : "memory");
        }
    }

    const int i = r0 + t;
    if (t < nv) {
        int a, h, k, l; float w;
        if (full) {
            a = s_in_asu[t];
            h = s_in_hkl[3 * t + 0];
            k = s_in_hkl[3 * t + 1];
            l = s_in_hkl[3 * t + 2];
            w = s_in_wl[t];
        } else {
            a = asu_id[i];
            h = hkl[3 * i + 0];
            k = hkl[3 * i + 1];
            l = hkl[3 * i + 2];
            w = wl[i];
        }

        const int ah = abs(h), ak = abs(k), al = abs(l);
        const bool mask = ((ah | ak | al) != 0);

        // gcd via shared table (|h|,|k|,|l| <= 12)
        const int g1 = sg[ah * 13 + ak];
        const int n  = sg[g1 * 13 + al];
        const int ns = max(n, 1);

        // exact division via reciprocal multiply (quotient exact small int)
        const float rcp = srcp[ns];
        const int h0 = __float2int_rn((float)h * rcp);
        const int k0 = __float2int_rn((float)k * rcp);
        const int l0 = __float2int_rn((float)l * rcp);

        const float wl0 = w * (float)ns;

        const float* Bm = sB + a * 9;
        const float fh = (float)h0, fk = (float)k0, fl = (float)l0;
        const float s0 = Bm[0] * fh + Bm[1] * fk + Bm[2] * fl;
        const float s1 = Bm[3] * fh + Bm[4] * fk + Bm[5] * fl;
        const float s2 = Bm[6] * fh + Bm[7] * fk + Bm[8] * fl;
        const float nrm2 = s0 * s0 + s1 * s1 + s2 * s2;
        const float d0   = rsqrtf(fmaxf(nrm2, 1e-12f));

        const float nmax = fminf(floorf(d0 * srdmin[a]), floorf(wl0 * INV_WMIN));
        const float nmin = floorf(wl0 * INV_WMAX) + 1.0f;

        const int step  = (h0 * G_C + k0) * G_C + l0;
        const int base0 = a * (G_C * G_C * G_C) + HMAX_C * (G_C * G_C + G_C + 1);
        const int m = max(max(abs(h0), abs(k0)), abs(l0));

        // Phase A: issue ALL gathers first (MLP on the L2-hit chain)
        int ni_a[MAX_MULT_C];
        int rid [MAX_MULT_C];
        #pragma unroll
        for (int j = 0; j < MAX_MULT_C; j++) {
            float na = nmin + (float)j;
            if (na > nmax) na = 0.0f;
            const int ni = (int)na;     // 0..17
            ni_a[j] = ni;
            rid[j] = -1;
            // ni==0 hits the table center which is always -1 -> skip the load
            if (ni > 0 && ni * m <= HMAX_C)
                rid[j] = ldg_policy(&refl[base0 + ni * step], pol_keep);
        }

        // Phase B: consume gathers, stage outputs
        #pragma unroll
        for (int j = 0; j < MAX_MULT_C; j++) {
            const int ni = ni_a[j];
            const bool absent = (rid[j] < 0);
            const int   ne   = absent ? 0 : ni;          // na>=1 when !absent
            const float ninv = absent ? 0.0f : srcp[ni]; // == 1.0f/na exactly

            s_hkl[t * 15 + 3 * j + 0] = (float)(h0 * ne);
            s_hkl[t * 15 + 3 * j + 1] = (float)(k0 * ne);
            s_hkl[t * 15 + 3 * j + 2] = (float)(l0 * ne);
            s_wl [t * 5 + j] = wl0 * ninv;
            s_d  [t * 5 + j] = d0  * ninv;
            s_id [t * 5 + j] = (float)(mask ? rid[j] : 0);
        }
    }
    __syncthreads();

    // ---- Copy-out ----
    const long b15 = (long)nv * 15 * 4;   // bytes
    const long b5  = (long)nv * 5 * 4;

    const bool tma_ok = ((b15 & 15) == 0) && ((b5 & 15) == 0) &&
                        ((((long)N * 60) & 15) == 0) && ((((long)r0 * 20) & 15) == 0);

    if (tma_ok) {
        if (t == 0) {
            uint64_t pol_stream;
            asm volatile("createpolicy.fractional.L2::evict_first.b64 %0, 1.0;"
                         : "=l"(pol_stream));
            asm volatile("fence.proxy.async.shared::cta;" ::: "memory");
            bulk_store_s2g_ef(out + (size_t)r0 * 15,                 s_hkl, (int)b15, pol_stream);
            bulk_store_s2g_ef(out + (size_t)N * 15 + (size_t)r0 * 5, s_wl,  (int)b5,  pol_stream);
            bulk_store_s2g_ef(out + (size_t)N * 20 + (size_t)r0 * 5, s_d,   (int)b5,  pol_stream);
            bulk_store_s2g_ef(out + (size_t)N * 25 + (size_t)r0 * 5, s_id,  (int)b5,  pol_stream);
            asm volatile("cp.async.bulk.commit_group;" ::: "memory");
            asm volatile("cp.async.bulk.wait_group.read 0;" ::: "memory");
        }
    } else {
        float* o0 = out + (size_t)r0 * 15;
        float* o1 = out + (size_t)N * 15 + (size_t)r0 * 5;
        float* o2 = out + (size_t)N * 20 + (size_t)r0 * 5;
        float* o3 = out + (size_t)N * 25 + (size_t)r0 * 5;
        for (int idx = t; idx < nv * 15; idx += BLOCK) o0[idx] = s_hkl[idx];
        for (int idx = t; idx < nv * 5;  idx += BLOCK) o1[idx] = s_wl[idx];
        for (int idx = t; idx < nv * 5;  idx += BLOCK) o2[idx] = s_d[idx];
        for (int idx = t; idx < nv * 5;  idx += BLOCK) o3[idx] = s_id[idx];
    }
}

extern "C" void kernel_launch(void* const* d_in, const int* in_sizes, int n_in,
                              void* d_out, int out_size)
{
    const int*   asu_id = (const int*)  d_in[0];
    const int*   hkl    = (const int*)  d_in[1];
    const float* wl     = (const float*)d_in[2];
    const float* dmin   = (const float*)d_in[3];
    const float* Bmat   = (const float*)d_in[4];
    const int*   refl   = (const int*)  d_in[5];

    const int N = in_sizes[0];
    float* out = (float*)d_out;

    const int grid = (N + BLOCK - 1) / BLOCK;
    expand_harmonics_kernel<<<grid, BLOCK>>>(asu_id, hkl, wl, dmin, Bmat, refl, out, N);
}

// round 16
// speedup vs baseline: 1.1216x; 1.1216x over previous
#include <cuda_runtime.h>
#include <cstdint>

// ExpandHarmonics: N=2e6 rows, MAX_MULT=5 harmonics per row.
// Output layout (concatenated flattened tuple, float32):
//   [0,15N) hkl_all | [15N,20N) wavelength_all | [20N,25N) d_all | [25N,30N) refl_id

#define HMAX_C 60
#define G_C    121
#define MAX_MULT_C 5
#define BLOCK 128

#define INV_WMIN (1.0f / 0.95f)
#define INV_WMAX 0.8f            // 1/1.25

// gcd table for a,b in [0,12]
__device__ const unsigned char GTAB[169] = {
    0,1,2,3,4,5,6,7,8,9,10,11,12,
    1,1,1,1,1,1,1,1,1,1,1,1,1,
    2,1,2,1,2,1,2,1,2,1,2,1,2,
    3,1,1,3,1,1,3,1,1,3,1,1,3,
    4,1,2,1,4,1,2,1,4,1,2,1,4,
    5,1,1,1,1,5,1,1,1,1,5,1,1,
    6,1,2,3,2,1,6,1,2,3,2,1,6,
    7,1,1,1,1,1,1,7,1,1,1,1,1,
    8,1,2,1,4,1,2,1,8,1,2,1,4,
    9,1,1,3,1,1,3,1,1,9,1,1,3,
    10,1,2,1,2,5,2,1,2,1,10,1,2,
    11,1,1,1,1,1,1,1,1,1,1,11,1,
    12,1,2,3,4,1,6,1,4,3,2,1,12
};

// Table gather with evict_last policy (keeps the 28MB table L2-resident
// against the 240MB streaming-store flood).
__device__ __forceinline__ int ldg_policy(const int* p, uint64_t policy) {
    int v;
    asm volatile("ld.global.nc.L2::cache_hint.b32 %0, [%1], %2;"
                 : "=r"(v) : "l"(p), "l"(policy));
    return v;
}

// Bulk store with evict_first policy: the write stream is touch-once.
__device__ __forceinline__ void bulk_store_s2g_ef(void* gdst, const void* ssrc, int bytes,
                                                  uint64_t policy) {
    uint32_t s = (uint32_t)__cvta_generic_to_shared(ssrc);
    asm volatile("cp.async.bulk.global.shared::cta.bulk_group.L2::cache_hint"
                 " [%0], [%1], %2, %3;"
                 :: "l"(gdst), "r"(s), "r"(bytes), "l"(policy) : "memory");
}

__global__ __launch_bounds__(BLOCK, 8)
void expand_harmonics_kernel(const int*   __restrict__ asu_id,
                             const int*   __restrict__ hkl,
                             const float* __restrict__ wl,
                             const float* __restrict__ dmin,
                             const float* __restrict__ Bmat,
                             const int*   __restrict__ refl,
                             float*       __restrict__ out,
                             int N)
{
    __shared__ float sB[36];
    __shared__ float srdmin[4];          // exact 1/dmin[a]
    __shared__ float srcp[32];           // 1/max(t,1): exact IEEE rcp of small ints
    __shared__ unsigned char sg[169];
    __shared__ __align__(16) float s_hkl[BLOCK * 15];
    __shared__ __align__(16) float s_wl [BLOCK * 5];
    __shared__ __align__(16) float s_d  [BLOCK * 5];
    __shared__ __align__(16) float s_id [BLOCK * 5];

    const int t = threadIdx.x;
    if (t < 36)  sB[t] = Bmat[t];
    if (t < 4)   srdmin[t] = 1.0f / dmin[t];
    if (t < 32)  srcp[t] = 1.0f / (float)max(t, 1);
    {
        if (t < 128)       sg[t]       = GTAB[t];
        if (t < 169 - 128) sg[t + 128] = GTAB[t + 128];
    }
    __syncthreads();

    // evict_last policy for table gathers (uniform; cheap)
    uint64_t pol_keep;
    asm volatile("createpolicy.fractional.L2::evict_last.b64 %0, 1.0;" : "=l"(pol_keep));

    const int r0 = blockIdx.x * BLOCK;
    const int nv = min(BLOCK, N - r0);
    const int i  = r0 + t;

    if (t < nv) {
        const int a = asu_id[i];
        const int h = hkl[3 * i + 0];
        const int k = hkl[3 * i + 1];
        const int l = hkl[3 * i + 2];
        const float w = wl[i];

        const int ah = abs(h), ak = abs(k), al = abs(l);
        const bool mask = ((ah | ak | al) != 0);

        // gcd via shared table (|h|,|k|,|l| <= 12)
        const int g1 = sg[ah * 13 + ak];
        const int n  = sg[g1 * 13 + al];
        const int ns = max(n, 1);

        // exact division via reciprocal multiply (quotient exact small int)
        const float rcp = srcp[ns];
        const int h0 = __float2int_rn((float)h * rcp);
        const int k0 = __float2int_rn((float)k * rcp);
        const int l0 = __float2int_rn((float)l * rcp);

        const float wl0 = w * (float)ns;

        const float* Bm = sB + a * 9;
        const float fh = (float)h0, fk = (float)k0, fl = (float)l0;
        const float s0 = Bm[0] * fh + Bm[1] * fk + Bm[2] * fl;
        const float s1 = Bm[3] * fh + Bm[4] * fk + Bm[5] * fl;
        const float s2 = Bm[6] * fh + Bm[7] * fk + Bm[8] * fl;
        const float nrm2 = s0 * s0 + s1 * s1 + s2 * s2;
        const float d0   = rsqrtf(fmaxf(nrm2, 1e-12f));

        const float nmax = fminf(floorf(d0 * srdmin[a]), floorf(wl0 * INV_WMIN));
        const float nmin = floorf(wl0 * INV_WMAX) + 1.0f;

        const int step  = (h0 * G_C + k0) * G_C + l0;
        const int base0 = a * (G_C * G_C * G_C) + HMAX_C * (G_C * G_C + G_C + 1);
        const int m = max(max(abs(h0), abs(k0)), abs(l0));

        // Phase A: issue ALL gathers first (MLP on the L2-hit chain)
        int ni_a[MAX_MULT_C];
        int rid [MAX_MULT_C];
        #pragma unroll
        for (int j = 0; j < MAX_MULT_C; j++) {
            float na = nmin + (float)j;
            if (na > nmax) na = 0.0f;
            const int ni = (int)na;     // 0..17
            ni_a[j] = ni;
            rid[j] = -1;
            // ni==0 hits the table center which is always -1 -> skip the load
            if (ni > 0 && ni * m <= HMAX_C)
                rid[j] = ldg_policy(&refl[base0 + ni * step], pol_keep);
        }

        // Phase B: consume gathers, stage outputs
        #pragma unroll
        for (int j = 0; j < MAX_MULT_C; j++) {
            const int ni = ni_a[j];
            const bool absent = (rid[j] < 0);
            const int   ne   = absent ? 0 : ni;          // na>=1 when !absent
            const float ninv = absent ? 0.0f : srcp[ni]; // == 1.0f/na exactly

            s_hkl[t * 15 + 3 * j + 0] = (float)(h0 * ne);
            s_hkl[t * 15 + 3 * j + 1] = (float)(k0 * ne);
            s_hkl[t * 15 + 3 * j + 2] = (float)(l0 * ne);
            s_wl [t * 5 + j] = wl0 * ninv;
            s_d  [t * 5 + j] = d0  * ninv;
            s_id [t * 5 + j] = (float)(mask ? rid[j] : 0);
        }
    }
    __syncthreads();

    // ---- Copy-out: 4 bulk stores distributed over 4 warps (parallel
    //      issue + parallel drains instead of a serial chain on thread 0) ----
    const long b15 = (long)nv * 15 * 4;   // bytes
    const long b5  = (long)nv * 5 * 4;

    const bool tma_ok = ((b15 & 15) == 0) && ((b5 & 15) == 0) &&
                        ((((long)N * 60) & 15) == 0) && ((((long)r0 * 20) & 15) == 0);

    if (tma_ok) {
        if ((t & 31) == 0) {
            const int wg = t >> 5;            // 0..3
            uint64_t pol_stream;
            asm volatile("createpolicy.fractional.L2::evict_first.b64 %0, 1.0;"
                         : "=l"(pol_stream));
            asm volatile("fence.proxy.async.shared::cta;" ::: "memory");
            if      (wg == 0) bulk_store_s2g_ef(out + (size_t)r0 * 15,                 s_hkl, (int)b15, pol_stream);
            else if (wg == 1) bulk_store_s2g_ef(out + (size_t)N * 15 + (size_t)r0 * 5, s_wl,  (int)b5,  pol_stream);
            else if (wg == 2) bulk_store_s2g_ef(out + (size_t)N * 20 + (size_t)r0 * 5, s_d,   (int)b5,  pol_stream);
            else              bulk_store_s2g_ef(out + (size_t)N * 25 + (size_t)r0 * 5, s_id,  (int)b5,  pol_stream);
            asm volatile("cp.async.bulk.commit_group;" ::: "memory");
            // Only this thread's group's smem READS must finish before the
            // CTA's smem can be reassigned.
            asm volatile("cp.async.bulk.wait_group.read 0;" ::: "memory");
        }
    } else {
        float* o0 = out + (size_t)r0 * 15;
        float* o1 = out + (size_t)N * 15 + (size_t)r0 * 5;
        float* o2 = out + (size_t)N * 20 + (size_t)r0 * 5;
        float* o3 = out + (size_t)N * 25 + (size_t)r0 * 5;
        for (int idx = t; idx < nv * 15; idx += BLOCK) o0[idx] = s_hkl[idx];
        for (int idx = t; idx < nv * 5;  idx += BLOCK) o1[idx] = s_wl[idx];
        for (int idx = t; idx < nv * 5;  idx += BLOCK) o2[idx] = s_d[idx];
        for (int idx = t; idx < nv * 5;  idx += BLOCK) o3[idx] = s_id[idx];
    }
}

extern "C" void kernel_launch(void* const* d_in, const int* in_sizes, int n_in,
                              void* d_out, int out_size)
{
    const int*   asu_id = (const int*)  d_in[0];
    const int*   hkl    = (const int*)  d_in[1];
    const float* wl     = (const float*)d_in[2];
    const float* dmin   = (const float*)d_in[3];
    const float* Bmat   = (const float*)d_in[4];
    const int*   refl   = (const int*)  d_in[5];

    const int N = in_sizes[0];
    float* out = (float*)d_out;

    const int grid = (N + BLOCK - 1) / BLOCK;
    expand_harmonics_kernel<<<grid, BLOCK>>>(asu_id, hkl, wl, dmin, Bmat, refl, out, N);
}